// round 10
// baseline (speedup 1.0000x reference)
#include <cuda_runtime.h>
#include <cstdint>

// ---------------------------------------------------------------------------
// BasicBlock_Sparse: two sparse-coding layers + shortcut, fp32.
// NUMERICAL CONTRACT: encoder conv accumulation is a SINGLE sequential FMA
// chain per output, ascending k = (ky, kx, c) with c fastest (bit-matches
// XLA-CPU/Eigen im2col GEMM -> identical top-k selection). fma.rn.f32x2
// performs two independent IEEE fmas; accumulators hold PIXEL pairs and the
// filter operand is pre-duplicated, so each (pixel,filter) chain is still a
// plain sequential fmaf chain -> bit-exact.
// ---------------------------------------------------------------------------

#define NIMG 64
#define F    512
#define OHW  28
#define NPIX (NIMG*OHW*OHW)      // 50176
#define COUT 128
#define OUTN ((size_t)NPIX*COUT) // 6422528
#define BN_EPS 1e-5f

typedef unsigned long long u64;

// ------------------------- device scratch (static) -------------------------
__device__ float g_a[(size_t)NPIX*F];       // encoder activations [pix][F]
__device__ float g_spval[NPIX*32];
__device__ int   g_spidx[NPIX*32];
__device__ int   g_spcnt[NPIX];
__device__ float g_out0[OUTN];              // layer0 output (pre then normalized)
__device__ float g_p1[OUTN];                // layer1 proj pre-BN
__device__ float g_psc[OUTN];               // shortcut pre-BN
__device__ u64   g_wTd0[576*512];           // enc0 weights [k][F], value DUPLICATED in u64
__device__ u64   g_wTd1[1152*512];          // enc1 weights [k][F], duplicated
__device__ float g_wr0[9*512*64];           // enc0 weights [kykx][F][C] for recon
__device__ float g_wr1[9*512*128];          // enc1 weights [kykx][F][C]
__device__ float g_wpT0[512*128];           // proj0 weights [F][COUT]
__device__ float g_wpT1[512*128];           // proj1 weights [F][COUT]
__device__ float g_wscT[64*128];            // shortcut weights [C][COUT]
__device__ float g_partial[NPIX];           // block partial sums (aux)
__device__ double2 g_bns[128*16];           // BN stage-1 partials
__device__ float g_mean[3][128];            // BN mean per slot {out0, p1, sc}
__device__ float g_rstd[3][128];            // BN rsqrt(var+eps) per slot

// ------------------------- asm helpers -------------------------------------
__device__ __forceinline__ void ffma2(u64& d, u64 a, u64 b) {
    asm("fma.rn.f32x2 %0, %1, %2, %0;" : "+l"(d) : "l"(a), "l"(b));
}
__device__ __forceinline__ void unpack2(u64 v, float& lo, float& hi) {
    unsigned a, b;
    asm("mov.b64 {%0, %1}, %2;" : "=r"(a), "=r"(b) : "l"(v));
    lo = __uint_as_float(a);
    hi = __uint_as_float(b);
}
__device__ __forceinline__ void cp4(unsigned dst, const float* src) {
    asm volatile("cp.async.ca.shared.global [%0], [%1], 4;" :: "r"(dst), "l"(src));
}
__device__ __forceinline__ void cp8(unsigned dst, const u64* src) {
    asm volatile("cp.async.ca.shared.global [%0], [%1], 8;" :: "r"(dst), "l"(src));
}
__device__ __forceinline__ void cp_commit() {
    asm volatile("cp.async.commit_group;");
}
__device__ __forceinline__ void cp_wait0() {
    asm volatile("cp.async.wait_group 0;");
}
// monotonic float->uint transform (order-preserving, strictly)
__device__ __forceinline__ unsigned fkey(float f) {
    unsigned b = __float_as_uint(f);
    return b ^ (unsigned)(((int)b >> 31) | 0x80000000);
}

// ------------------------- fused weight re-layout --------------------------
// wTd[k][f] (k=(ky,kx,c), c fastest), each fp32 duplicated into a u64 so the
// conv loader can cp.async 8B of pre-dupped filter operand.
__global__ void prep_enc(const float* __restrict__ w, int CIN, int which) {
    u64*   wTd = which ? g_wTd1 : g_wTd0;
    float* wr  = which ? g_wr1  : g_wr0;
    int tot = 9 * 512 * CIN;
    int i = blockIdx.x * 256 + threadIdx.x;
    if (i >= tot) return;
    {
        int k = i / 512, f = i - k * 512;
        int ky = k / (3 * CIN);
        int r  = k - ky * 3 * CIN;
        int kx = r / CIN;
        int c  = r - kx * CIN;
        unsigned b = __float_as_uint(w[(f * CIN + c) * 9 + ky * 3 + kx]);
        wTd[i] = ((u64)b << 32) | b;
    }
    {
        int c = i % CIN;
        int f = (i / CIN) % 512;
        int r = i / (CIN * 512);
        wr[i] = w[(f * CIN + c) * 9 + r];
    }
}
__global__ void make_wpT(const float* __restrict__ wp, int which) {
    float* dst = which ? g_wpT1 : g_wpT0;
    int i = blockIdx.x * 256 + threadIdx.x;
    if (i >= 512 * 128) return;
    int f = i / 128, co = i - f * 128;
    dst[i] = wp[co * 512 + f];
}
__global__ void make_wscT(const float* __restrict__ w) {
    int i = blockIdx.x * 256 + threadIdx.x;
    if (i >= 64 * 128) return;
    int c = i / 128, co = i - c * 128;
    g_wscT[i] = w[co * 64 + c];
}

// ------------------------- encoder conv (implicit GEMM, f32x2) -------------
// Tile: BM=128 pixels x BN=128 filters x BK=8, 128 threads, microtile 16x8.
// Accumulators are pixel-pairs; filter operand pre-duplicated in smem ->
// inner loop has ZERO duplication movs: 64 FFMA2 + 8 LDS.128 per kk.
template<int CIN, int STRIDE, int HIN, bool L1>
__global__ void __launch_bounds__(128, 2) conv_enc(const float* __restrict__ xin) {
    const int K = CIN * 9;
    const int NT = K / 8;
    const float* __restrict__ src = L1 ? (const float*)g_out0 : xin;
    const u64* __restrict__ wTd = L1 ? g_wTd1 : g_wTd0;

    __shared__ float As[2][8][128];     // 8 KB
    __shared__ u64   Bs[2][8][128];     // 16 KB (dupped filters)
    __shared__ int   sBase[128];
    __shared__ int   sOy[128];
    __shared__ int   sOx[128];

    int tid = threadIdx.x;       // 0..127
    int bm = blockIdx.x, bn = blockIdx.y;

    {
        int p = bm * 128 + tid;
        int n = p / 784;
        int r = p - n * 784;
        int oy = r / 28, ox = r - oy * 28;
        sOy[tid] = oy * STRIDE;
        sOx[tid] = ox * STRIDE;
        sBase[tid] = n * CIN * HIN * HIN + oy * STRIDE * HIN + ox * STRIDE;
    }
    __syncthreads();

    int m = tid;                 // loader column (pixel for A, filter for B)
    int base_m = sBase[m], oyS = sOy[m], oxS = sOx[m];

    unsigned aAddr = (unsigned)__cvta_generic_to_shared(&As[0][0][m]);
    unsigned bAddr = (unsigned)__cvta_generic_to_shared(&Bs[0][0][m]);
    const int aBuf = 8 * 128 * 4, aRow = 128 * 4;
    const int bBuf = 8 * 128 * 8, bRow = 128 * 8;

    int trow = tid >> 4;         // 0..7  -> 16 pixels (8 pairs)
    int tcol = tid & 15;         // 0..15 -> 8 filters

    u64 acc[8][8];               // [pixel pair][filter]
#pragma unroll
    for (int i = 0; i < 8; i++)
#pragma unroll
        for (int j = 0; j < 8; j++) acc[i][j] = 0ULL;

    auto issue_tile = [&](int t, int buf) {
        int kt = t * 8;
        int ky = kt / (3 * CIN);
        int rr = kt - ky * 3 * CIN;
        int kx = rr / CIN;
        int c0 = rr - kx * CIN;
        int iy = oyS + ky - 1, ix = oxS + kx - 1;
        bool valid = ((unsigned)iy < (unsigned)HIN) && ((unsigned)ix < (unsigned)HIN);
        const float* ap = src + base_m + (ky - 1) * HIN + (kx - 1);
        const u64* bp = wTd + (size_t)kt * F + bn * 128 + m;
        unsigned ab = aAddr + buf * aBuf;
        unsigned bb = bAddr + buf * bBuf;
        if (valid) {
#pragma unroll
            for (int kl = 0; kl < 8; kl++)
                cp4(ab + kl * aRow, ap + (c0 + kl) * HIN * HIN);
        } else {
#pragma unroll
            for (int kl = 0; kl < 8; kl++)
                As[buf][kl][m] = 0.f;
        }
#pragma unroll
        for (int kl = 0; kl < 8; kl++)
            cp8(bb + kl * bRow, bp + (size_t)kl * F);
        cp_commit();
    };

    issue_tile(0, 0);

    for (int t = 0; t < NT; t++) {
        cp_wait0();
        __syncthreads();             // tile t visible; compute t-1 done
        if (t + 1 < NT) issue_tile(t + 1, (t + 1) & 1);

        int cur = t & 1;
#pragma unroll
        for (int kk = 0; kk < 8; kk++) {
            // A: 16 adjacent pixels as 8 u64 pairs (no movs)
            const ulonglong2* a2 = reinterpret_cast<const ulonglong2*>(&As[cur][kk][trow * 16]);
            ulonglong2 p01 = a2[0], p23 = a2[1], p45 = a2[2], p67 = a2[3];
            u64 ap8[8] = {p01.x, p01.y, p23.x, p23.y, p45.x, p45.y, p67.x, p67.y};
            // B: 8 pre-dupped filters as u64 (no movs)
            const ulonglong2* b2 = reinterpret_cast<const ulonglong2*>(&Bs[cur][kk][tcol * 8]);
            ulonglong2 q01 = b2[0], q23 = b2[1], q45 = b2[2], q67 = b2[3];
            u64 bd[8] = {q01.x, q01.y, q23.x, q23.y, q45.x, q45.y, q67.x, q67.y};
#pragma unroll
            for (int i = 0; i < 8; i++)
#pragma unroll
                for (int j = 0; j < 8; j++)
                    ffma2(acc[i][j], ap8[i], bd[j]);
        }
    }

    // epilogue: each acc[pp][j] = (pixel 2pp, pixel 2pp+1) x filter j
    int f0 = bn * 128 + tcol * 8;
#pragma unroll
    for (int pp = 0; pp < 8; pp++) {
        float lo[8], hi[8];
#pragma unroll
        for (int j = 0; j < 8; j++) unpack2(acc[pp][j], lo[j], hi[j]);
        int pix0 = bm * 128 + trow * 16 + 2 * pp;
        float* d0 = &g_a[(size_t)pix0 * F + f0];
        float* d1 = &g_a[(size_t)(pix0 + 1) * F + f0];
        *(float4*)d0       = make_float4(lo[0], lo[1], lo[2], lo[3]);
        *(float4*)(d0 + 4) = make_float4(lo[4], lo[5], lo[6], lo[7]);
        *(float4*)d1       = make_float4(hi[0], hi[1], hi[2], hi[3]);
        *(float4*)(d1 + 4) = make_float4(hi[4], hi[5], hi[6], hi[7]);
    }
}

// ------------------------- exact top-k (sorted lanes + redux) --------------
#define CE(i, j) { unsigned x_ = u[i], y_ = u[j]; \
                   u[i] = x_ > y_ ? x_ : y_; u[j] = x_ > y_ ? y_ : x_; }

__global__ void __launch_bounds__(256) topk_kernel() {
    int warp = blockIdx.x * 8 + (threadIdx.x >> 5);
    int lane = threadIdx.x & 31;
    if (warp >= NPIX) return;
    const float* ap = g_a + (size_t)warp * F;

    float v[16];
#pragma unroll
    for (int j = 0; j < 16; j++) v[j] = ap[j * 32 + lane];

    unsigned u[16];
#pragma unroll
    for (int j = 0; j < 16; j++) u[j] = fkey(v[j]);

    // Batcher odd-even mergesort, 16 elements, descending (63 CEs)
    CE(0,1) CE(2,3) CE(4,5) CE(6,7) CE(8,9) CE(10,11) CE(12,13) CE(14,15)
    CE(0,2) CE(1,3) CE(4,6) CE(5,7) CE(8,10) CE(9,11) CE(12,14) CE(13,15)
    CE(1,2) CE(5,6) CE(9,10) CE(13,14)
    CE(0,4) CE(1,5) CE(2,6) CE(3,7) CE(8,12) CE(9,13) CE(10,14) CE(11,15)
    CE(2,4) CE(3,5) CE(10,12) CE(11,13)
    CE(1,2) CE(3,4) CE(5,6) CE(9,10) CE(11,12) CE(13,14)
    CE(0,8) CE(1,9) CE(2,10) CE(3,11) CE(4,12) CE(5,13) CE(6,14) CE(7,15)
    CE(4,8) CE(5,9) CE(6,10) CE(7,11)
    CE(2,4) CE(3,5) CE(6,8) CE(7,9) CE(10,12) CE(11,13)
    CE(1,2) CE(3,4) CE(5,6) CE(7,8) CE(9,10) CE(11,12) CE(13,14)

    int removed = 0;
    unsigned Tu = 0;
#pragma unroll 1
    for (int it = 0; it < 16; it++) {
        unsigned h = u[0];
        unsigned mx = __reduce_max_sync(0xffffffffu, h);
        int c = __popc(__ballot_sync(0xffffffffu, h == mx));
        Tu = mx;
        if (removed + c >= 16) break;
        removed += c;
        if (h == mx) {
#pragma unroll
            for (int j = 0; j < 15; j++) u[j] = u[j + 1];
            u[15] = 0u;
        }
    }

    int base = 0;
#pragma unroll
    for (int j = 0; j < 16; j++) {
        bool keep = fkey(v[j]) >= Tu;
        unsigned bal = __ballot_sync(0xffffffffu, keep);
        if (keep) {
            int pos = base + __popc(bal & ((1u << lane) - 1u));
            if (pos < 32) {
                g_spidx[warp * 32 + pos] = j * 32 + lane;
                g_spval[warp * 32 + pos] = v[j];
            }
        }
        base += __popc(bal);
    }
    if (lane == 0) g_spcnt[warp] = base < 32 ? base : 32;
}
#undef CE

// ------------------------- sparse adjoint recon + aux (float4/channel) -----
template<int CIN, int STRIDE, int HIN, bool L1>
__global__ void __launch_bounds__(256) recon_aux_kernel(const float* __restrict__ refp) {
    const int TPP = CIN / 4;            // threads per pixel
    const int PPB = 256 / TPP;          // pixels per block
    int tid = threadIdx.x;
    int cg = tid % TPP;
    int c0 = cg * 4;
    int pi = tid / TPP;
    int g = blockIdx.x * PPB + pi;
    int n = g / (HIN * HIN);
    int r = g - n * (HIN * HIN);
    int y = r / HIN, xx = r - y * HIN;
    const float* wrb = L1 ? g_wr1 : g_wr0;

    float4 recon = {0.f, 0.f, 0.f, 0.f};
#pragma unroll
    for (int ky = 0; ky < 3; ky++) {
        int t = y + 1 - ky;
        int oy;
        if (STRIDE == 2) { if (t & 1) continue; oy = t >> 1; } else oy = t;
        if ((unsigned)oy >= 28u) continue;
#pragma unroll
        for (int kx = 0; kx < 3; kx++) {
            int s = xx + 1 - kx;
            int ox;
            if (STRIDE == 2) { if (s & 1) continue; ox = s >> 1; } else ox = s;
            if ((unsigned)ox >= 28u) continue;
            int q = (n * 28 + oy) * 28 + ox;
            int cnt = g_spcnt[q];
            const float* wb = wrb + (size_t)(ky * 3 + kx) * F * CIN + c0;
            const int4*   ip = (const int4*)&g_spidx[q * 32];
            const float4* vp = (const float4*)&g_spval[q * 32];
            int nb = cnt >> 2;
            for (int b = 0; b < nb; b++) {
                int4   f4 = ip[b];
                float4 v4 = vp[b];
                float4 w0 = *(const float4*)&wb[f4.x * CIN];
                float4 w1 = *(const float4*)&wb[f4.y * CIN];
                float4 w2 = *(const float4*)&wb[f4.z * CIN];
                float4 w3 = *(const float4*)&wb[f4.w * CIN];
                recon.x += v4.x * w0.x; recon.y += v4.x * w0.y;
                recon.z += v4.x * w0.z; recon.w += v4.x * w0.w;
                recon.x += v4.y * w1.x; recon.y += v4.y * w1.y;
                recon.z += v4.y * w1.z; recon.w += v4.y * w1.w;
                recon.x += v4.z * w2.x; recon.y += v4.z * w2.y;
                recon.z += v4.z * w2.z; recon.w += v4.z * w2.w;
                recon.x += v4.w * w3.x; recon.y += v4.w * w3.y;
                recon.z += v4.w * w3.z; recon.w += v4.w * w3.w;
            }
            for (int e = nb * 4; e < cnt; e++) {
                float vv = g_spval[q * 32 + e];
                const float4 ww = *(const float4*)&wb[g_spidx[q * 32 + e] * CIN];
                recon.x += vv * ww.x; recon.y += vv * ww.y;
                recon.z += vv * ww.z; recon.w += vv * ww.w;
            }
        }
    }
    const float* refbase = L1 ? (const float*)g_out0 : refp;
    size_t ridx = ((size_t)(n * CIN + c0) * HIN + y) * HIN + xx;
    const size_t cs = (size_t)HIN * HIN;
    float d0 = recon.x - refbase[ridx];
    float d1 = recon.y - refbase[ridx + cs];
    float d2 = recon.z - refbase[ridx + 2 * cs];
    float d3 = recon.w - refbase[ridx + 3 * cs];
    float dd = d0 * d0 + d1 * d1 + d2 * d2 + d3 * d3;

    __shared__ float red[256];
    red[tid] = dd;
    __syncthreads();
    for (int st = 128; st > 0; st >>= 1) {
        if (tid < st) red[tid] += red[tid + st];
        __syncthreads();
    }
    if (tid == 0) g_partial[blockIdx.x] = red[0];
}

__global__ void reduce_partials(int n, float scale, float* __restrict__ out) {
    __shared__ float red[256];
    float s = 0.f;
    for (int i = threadIdx.x; i < n; i += 256) s += g_partial[i];
    red[threadIdx.x] = s;
    __syncthreads();
    for (int st = 128; st > 0; st >>= 1) {
        if (threadIdx.x < st) red[threadIdx.x] += red[threadIdx.x + st];
        __syncthreads();
    }
    if (threadIdx.x == 0) *out = red[0] * scale;
}

// ------------------------- sparse 1x1 projection (unrolled x4) -------------
__global__ void __launch_bounds__(256) proj_kernel(int slot) {
    float* out = (slot == 0) ? g_out0 : g_p1;
    const float* wp = (slot == 0) ? g_wpT0 : g_wpT1;
    int tid = threadIdx.x;
    int co = tid & 127;
    int pi = tid >> 7;
    int q = blockIdx.x * 2 + pi;
    int cnt = g_spcnt[q];
    const int4*   ip = (const int4*)&g_spidx[q * 32];
    const float4* vp = (const float4*)&g_spval[q * 32];
    float acc = 0.f;
    int nb = cnt >> 2;
    for (int b = 0; b < nb; b++) {
        int4   f4 = ip[b];
        float4 v4 = vp[b];
        float w0 = wp[f4.x * COUT + co];
        float w1 = wp[f4.y * COUT + co];
        float w2 = wp[f4.z * COUT + co];
        float w3 = wp[f4.w * COUT + co];
        acc += v4.x * w0;
        acc += v4.y * w1;
        acc += v4.z * w2;
        acc += v4.w * w3;
    }
    for (int e = nb * 4; e < cnt; e++)
        acc += g_spval[q * 32 + e] * wp[g_spidx[q * 32 + e] * COUT + co];
    int n = q / 784, r = q - n * 784;
    out[(size_t)(n * COUT + co) * 784 + r] = acc;
}

// ------------------------- shortcut 1x1 stride-2 ---------------------------
__global__ void __launch_bounds__(256) shortcut_kernel(const float* __restrict__ x) {
    int tid = threadIdx.x;
    int co = tid & 127;
    int pi = tid >> 7;
    int q = blockIdx.x * 2 + pi;
    int n = q / 784, r = q - n * 784;
    int oy = r / 28, ox = r - oy * 28;
    const float* xp = x + (size_t)n * 64 * 3136 + (2 * oy) * 56 + 2 * ox;
    float acc = 0.f;
#pragma unroll
    for (int c = 0; c < 64; c++) acc = fmaf(xp[c * 3136], g_wscT[c * 128 + co], acc);
    g_psc[(size_t)(n * COUT + co) * 784 + r] = acc;
}

// ------------------------- batchnorm stats (two-stage, double) -------------
__global__ void __launch_bounds__(256) bn_stage1(int slot) {
    const float* src = (slot == 0) ? g_out0 : (slot == 1 ? g_p1 : g_psc);
    int co = blockIdx.x;
    int chunk = blockIdx.y;
    int tid = threadIdx.x;
    double s = 0.0, s2 = 0.0;
    for (int n = chunk * 4; n < chunk * 4 + 4; n++) {
        const float* row = src + (size_t)(n * COUT + co) * 784;
        for (int r = tid; r < 784; r += 256) {
            double v = (double)row[r];
            s += v; s2 += v * v;
        }
    }
    __shared__ double rs[256], rq[256];
    rs[tid] = s; rq[tid] = s2;
    __syncthreads();
    for (int st = 128; st > 0; st >>= 1) {
        if (tid < st) { rs[tid] += rs[tid + st]; rq[tid] += rq[tid + st]; }
        __syncthreads();
    }
    if (tid == 0) g_bns[co * 16 + chunk] = make_double2(rs[0], rq[0]);
}
__global__ void bn_stage2(int slot) {
    int co = threadIdx.x;
    double s = 0.0, s2 = 0.0;
    for (int k = 0; k < 16; k++) {
        double2 p = g_bns[co * 16 + k];
        s += p.x; s2 += p.y;
    }
    double mean = s * (1.0 / 50176.0);
    double var = s2 * (1.0 / 50176.0) - mean * mean;
    g_mean[slot][co] = (float)mean;
    g_rstd[slot][co] = rsqrtf((float)var + BN_EPS);
}

__global__ void __launch_bounds__(256) norm0_kernel(const float* __restrict__ gg,
                                                    const float* __restrict__ bb) {
    size_t i = (size_t)blockIdx.x * 256 + threadIdx.x;
    if (i >= OUTN) return;
    int co = (int)((i / 784) & 127);
    g_out0[i] = ((g_out0[i] - g_mean[0][co]) * g_rstd[0][co]) * gg[co] + bb[co];
}

__global__ void __launch_bounds__(256) final_kernel(float* __restrict__ dout,
        const float* __restrict__ g1, const float* __restrict__ b1,
        const float* __restrict__ gsc, const float* __restrict__ bsc) {
    size_t i = (size_t)blockIdx.x * 256 + threadIdx.x;
    if (i >= OUTN) return;
    int co = (int)((i / 784) & 127);
    float v1 = ((g_p1[i]  - g_mean[1][co]) * g_rstd[1][co]) * g1[co]  + b1[co];
    float v2 = ((g_psc[i] - g_mean[2][co]) * g_rstd[2][co]) * gsc[co] + bsc[co];
    float v = v1 + v2;
    dout[i] = v > 0.f ? v : 0.f;
}

// ---------------------------------------------------------------------------
extern "C" void kernel_launch(void* const* d_in, const int* in_sizes, int n_in,
                              void* d_out, int out_size) {
    const float* x       = (const float*)d_in[0];
    const float* w_enc0  = (const float*)d_in[1];
    const float* w_proj0 = (const float*)d_in[2];
    const float* g0      = (const float*)d_in[3];
    const float* b0      = (const float*)d_in[4];
    const float* w_enc1  = (const float*)d_in[5];
    const float* w_proj1 = (const float*)d_in[6];
    const float* g1      = (const float*)d_in[7];
    const float* b1      = (const float*)d_in[8];
    const float* w_sc    = (const float*)d_in[9];
    const float* g_sc    = (const float*)d_in[10];
    const float* b_sc    = (const float*)d_in[11];
    float* out = (float*)d_out;

    const int elem_blocks = (int)((OUTN + 255) / 256);
    dim3 bnGrid(128, 16);

    // ---------------- layer 0 ----------------
    prep_enc<<<(9 * 512 * 64 + 255) / 256, 256>>>(w_enc0, 64, 0);     // #1
    make_wpT<<<(512 * 128 + 255) / 256, 256>>>(w_proj0, 0);           // #2
    make_wscT<<<(64 * 128 + 255) / 256, 256>>>(w_sc);                 // #3
    conv_enc<64, 2, 56, false><<<dim3(NPIX / 128, 4), 128>>>(x);      // #4 <- profiled
    topk_kernel<<<NPIX / 8, 256>>>();
    recon_aux_kernel<64, 2, 56, false><<<NIMG * 3136 / 16, 256>>>(x);
    reduce_partials<<<1, 256>>>(NIMG * 3136 / 16, 1.f / 12845056.f, out + out_size - 2);
    proj_kernel<<<NPIX / 2, 256>>>(0);
    bn_stage1<<<bnGrid, 256>>>(0);
    bn_stage2<<<1, 128>>>(0);
    norm0_kernel<<<elem_blocks, 256>>>(g0, b0);

    // ---------------- layer 1 ----------------
    prep_enc<<<(9 * 512 * 128 + 255) / 256, 256>>>(w_enc1, 128, 1);
    conv_enc<128, 1, 28, true><<<dim3(NPIX / 128, 4), 128>>>(x);
    topk_kernel<<<NPIX / 8, 256>>>();
    recon_aux_kernel<128, 1, 28, true><<<NIMG * 784 / 8, 256>>>(nullptr);
    reduce_partials<<<1, 256>>>(NIMG * 784 / 8, 1.f / 6422528.f, out + out_size - 1);
    make_wpT<<<(512 * 128 + 255) / 256, 256>>>(w_proj1, 1);
    proj_kernel<<<NPIX / 2, 256>>>(1);
    bn_stage1<<<bnGrid, 256>>>(1);
    bn_stage2<<<1, 128>>>(1);

    // ---------------- shortcut + fuse ----------------
    shortcut_kernel<<<NPIX / 2, 256>>>(x);
    bn_stage1<<<bnGrid, 256>>>(2);
    bn_stage2<<<1, 128>>>(2);
    final_kernel<<<elem_blocks, 256>>>(out, g1, b1, g_sc, b_sc);
}

// round 12
// speedup vs baseline: 1.6351x; 1.6351x over previous
#include <cuda_runtime.h>
#include <cstdint>

// ---------------------------------------------------------------------------
// BasicBlock_Sparse: two sparse-coding layers + shortcut, fp32.
// NUMERICAL CONTRACT: encoder conv accumulation is a SINGLE sequential FMA
// chain per output, ascending k = (ky, kx, c) with c fastest (bit-matches
// XLA-CPU/Eigen im2col GEMM -> identical top-k selection). fma.rn.f32x2
// performs two independent IEEE fmas; accumulators hold PIXEL pairs (A read
// as natural u64 pairs from smem, B duplicated in registers), so each
// (pixel,filter) chain is a plain sequential fmaf chain -> bit-exact.
// ---------------------------------------------------------------------------

#define NIMG 64
#define F    512
#define OHW  28
#define NPIX (NIMG*OHW*OHW)      // 50176
#define COUT 128
#define OUTN ((size_t)NPIX*COUT) // 6422528
#define BN_EPS 1e-5f

typedef unsigned long long u64;

// ------------------------- device scratch (static) -------------------------
__device__ float g_a[(size_t)NPIX*F];       // encoder activations [pix][F]
__device__ float g_spval[NPIX*32];
__device__ int   g_spidx[NPIX*32];
__device__ int   g_spcnt[NPIX];
__device__ float g_out0[OUTN];              // layer0 output (pre then normalized)
__device__ float g_p1[OUTN];                // layer1 proj pre-BN
__device__ float g_psc[OUTN];               // shortcut pre-BN
__device__ float g_wT0[576*512];            // enc0 weights [k=(ky,kx,c)][F]
__device__ float g_wT1[1152*512];           // enc1 weights [k][F]
__device__ float g_wr0[9*512*64];           // enc0 weights [kykx][F][C] for recon
__device__ float g_wr1[9*512*128];          // enc1 weights [kykx][F][C]
__device__ float g_wpT0[512*128];           // proj0 weights [F][COUT]
__device__ float g_wpT1[512*128];           // proj1 weights [F][COUT]
__device__ float g_wscT[64*128];            // shortcut weights [C][COUT]
__device__ float g_partial[NPIX];           // block partial sums (aux)
__device__ double2 g_bns[128*16];           // BN stage-1 partials
__device__ float g_mean[3][128];            // BN mean per slot {out0, p1, sc}
__device__ float g_rstd[3][128];            // BN rsqrt(var+eps) per slot

// ------------------------- asm helpers -------------------------------------
__device__ __forceinline__ void ffma2(u64& d, u64 a, u64 b) {
    asm("fma.rn.f32x2 %0, %1, %2, %0;" : "+l"(d) : "l"(a), "l"(b));
}
__device__ __forceinline__ u64 dup2(float x) {
    u64 r;
    unsigned xi = __float_as_uint(x);
    asm("mov.b64 %0, {%1, %1};" : "=l"(r) : "r"(xi));
    return r;
}
__device__ __forceinline__ void unpack2(u64 v, float& lo, float& hi) {
    unsigned a, b;
    asm("mov.b64 {%0, %1}, %2;" : "=r"(a), "=r"(b) : "l"(v));
    lo = __uint_as_float(a);
    hi = __uint_as_float(b);
}
__device__ __forceinline__ void cp4(unsigned dst, const float* src) {
    asm volatile("cp.async.ca.shared.global [%0], [%1], 4;" :: "r"(dst), "l"(src));
}
__device__ __forceinline__ void cp_commit() {
    asm volatile("cp.async.commit_group;");
}
__device__ __forceinline__ void cp_wait0() {
    asm volatile("cp.async.wait_group 0;");
}
// monotonic float->uint transform (order-preserving, strictly)
__device__ __forceinline__ unsigned fkey(float f) {
    unsigned b = __float_as_uint(f);
    return b ^ (unsigned)(((int)b >> 31) | 0x80000000);
}

// ------------------------- fused weight re-layout --------------------------
__global__ void prep_enc(const float* __restrict__ w, int CIN, int which) {
    float* wT = which ? g_wT1 : g_wT0;
    float* wr = which ? g_wr1 : g_wr0;
    int tot = 9 * 512 * CIN;
    int i = blockIdx.x * 256 + threadIdx.x;
    if (i >= tot) return;
    {
        int k = i / 512, f = i - k * 512;
        int ky = k / (3 * CIN);
        int r  = k - ky * 3 * CIN;
        int kx = r / CIN;
        int c  = r - kx * CIN;
        wT[i] = w[(f * CIN + c) * 9 + ky * 3 + kx];
    }
    {
        int c = i % CIN;
        int f = (i / CIN) % 512;
        int r = i / (CIN * 512);
        wr[i] = w[(f * CIN + c) * 9 + r];
    }
}
__global__ void make_wpT(const float* __restrict__ wp, int which) {
    float* dst = which ? g_wpT1 : g_wpT0;
    int i = blockIdx.x * 256 + threadIdx.x;
    if (i >= 512 * 128) return;
    int f = i / 128, co = i - f * 128;
    dst[i] = wp[co * 512 + f];
}
__global__ void make_wscT(const float* __restrict__ w) {
    int i = blockIdx.x * 256 + threadIdx.x;
    if (i >= 64 * 128) return;
    int c = i / 128, co = i - c * 128;
    g_wscT[i] = w[co * 64 + c];
}

// ------------------------- encoder conv (implicit GEMM, f32x2) -------------
// Tile: BM=128 pixels x BN=128 filters x BK=16, 128 threads, microtile 16x8.
// Accumulators are pixel-pairs: A read as natural u64 pairs (no movs), only
// B duplicated in regs (8 movs/kk vs 16). smem 0.75 B/MAC (R10's 1.0 B/MAC
// dup-B-in-smem variant regressed: crossbar-bound).
template<int CIN, int STRIDE, int HIN, bool L1>
__global__ void __launch_bounds__(128, 2) conv_enc(const float* __restrict__ xin) {
    const int K = CIN * 9;
    const int NT = K / 16;
    const float* __restrict__ src = L1 ? (const float*)g_out0 : xin;
    const float* __restrict__ wT = L1 ? g_wT1 : g_wT0;

    __shared__ float As[2][16][128];
    __shared__ float Bs[2][16][128];
    __shared__ int   sBase[128];
    __shared__ int   sOy[128];
    __shared__ int   sOx[128];

    int tid = threadIdx.x;       // 0..127
    int bm = blockIdx.x, bn = blockIdx.y;

    {
        int p = bm * 128 + tid;
        int n = p / 784;
        int r = p - n * 784;
        int oy = r / 28, ox = r - oy * 28;
        sOy[tid] = oy * STRIDE;
        sOx[tid] = ox * STRIDE;
        sBase[tid] = n * CIN * HIN * HIN + oy * STRIDE * HIN + ox * STRIDE;
    }
    __syncthreads();

    int m = tid;                 // loader column (pixel for A, filter for B)
    int base_m = sBase[m], oyS = sOy[m], oxS = sOx[m];

    unsigned aAddr = (unsigned)__cvta_generic_to_shared(&As[0][0][m]);
    unsigned bAddr = (unsigned)__cvta_generic_to_shared(&Bs[0][0][m]);
    const int bufStride = 16 * 128 * 4;
    const int rowStride = 128 * 4;

    int trow = tid >> 4;         // 0..7  -> 16 pixels (8 pairs)
    int tcol = tid & 15;         // 0..15 -> 8 filters

    u64 acc[8][8];               // [pixel pair][filter]
#pragma unroll
    for (int i = 0; i < 8; i++)
#pragma unroll
        for (int j = 0; j < 8; j++) acc[i][j] = 0ULL;

    auto issue_tile = [&](int t, int buf) {
        int kt = t * 16;
        int ky = kt / (3 * CIN);
        int rr = kt - ky * 3 * CIN;
        int kx = rr / CIN;
        int c0 = rr - kx * CIN;
        int iy = oyS + ky - 1, ix = oxS + kx - 1;
        bool valid = ((unsigned)iy < (unsigned)HIN) && ((unsigned)ix < (unsigned)HIN);
        const float* ap = src + base_m + (ky - 1) * HIN + (kx - 1);
        const float* bp = wT + (size_t)kt * F + bn * 128 + m;
        unsigned ab = aAddr + buf * bufStride;
        unsigned bb = bAddr + buf * bufStride;
        if (valid) {
#pragma unroll
            for (int kl = 0; kl < 16; kl++)
                cp4(ab + kl * rowStride, ap + (c0 + kl) * HIN * HIN);
        } else {
#pragma unroll
            for (int kl = 0; kl < 16; kl++)
                As[buf][kl][m] = 0.f;
        }
#pragma unroll
        for (int kl = 0; kl < 16; kl++)
            cp4(bb + kl * rowStride, bp + kl * F);
        cp_commit();
    };

    issue_tile(0, 0);

    for (int t = 0; t < NT; t++) {
        cp_wait0();
        __syncthreads();             // tile t visible; compute t-1 done
        if (t + 1 < NT) issue_tile(t + 1, (t + 1) & 1);

        int cur = t & 1;
#pragma unroll
        for (int kk = 0; kk < 16; kk++) {
            // A: 16 adjacent pixels as 8 u64 pairs, straight from smem (no movs)
            const ulonglong2* a2 = reinterpret_cast<const ulonglong2*>(&As[cur][kk][trow * 16]);
            ulonglong2 p01 = a2[0], p23 = a2[1], p45 = a2[2], p67 = a2[3];
            u64 ap8[8] = {p01.x, p01.y, p23.x, p23.y, p45.x, p45.y, p67.x, p67.y};
            // B: 8 filters (float), duplicated in regs (8 movs)
            const float4* b4 = reinterpret_cast<const float4*>(&Bs[cur][kk][tcol * 8]);
            float4 b0 = b4[0], b1 = b4[1];
            u64 bd[8] = {dup2(b0.x), dup2(b0.y), dup2(b0.z), dup2(b0.w),
                         dup2(b1.x), dup2(b1.y), dup2(b1.z), dup2(b1.w)};
#pragma unroll
            for (int i = 0; i < 8; i++)
#pragma unroll
                for (int j = 0; j < 8; j++)
                    ffma2(acc[i][j], ap8[i], bd[j]);
        }
    }

    // epilogue: acc[pp][j] = (pixel 2pp, pixel 2pp+1) x filter j
    int f0 = bn * 128 + tcol * 8;
#pragma unroll
    for (int pp = 0; pp < 8; pp++) {
        float lo[8], hi[8];
#pragma unroll
        for (int j = 0; j < 8; j++) unpack2(acc[pp][j], lo[j], hi[j]);
        int pix0 = bm * 128 + trow * 16 + 2 * pp;
        float* d0 = &g_a[(size_t)pix0 * F + f0];
        float* d1 = &g_a[(size_t)(pix0 + 1) * F + f0];
        *(float4*)d0       = make_float4(lo[0], lo[1], lo[2], lo[3]);
        *(float4*)(d0 + 4) = make_float4(lo[4], lo[5], lo[6], lo[7]);
        *(float4*)d1       = make_float4(hi[0], hi[1], hi[2], hi[3]);
        *(float4*)(d1 + 4) = make_float4(hi[4], hi[5], hi[6], hi[7]);
    }
}

// ------------------------- exact top-k (sorted lanes + redux) --------------
#define CE(i, j) { unsigned x_ = u[i], y_ = u[j]; \
                   u[i] = x_ > y_ ? x_ : y_; u[j] = x_ > y_ ? y_ : x_; }

__global__ void __launch_bounds__(256) topk_kernel() {
    int warp = blockIdx.x * 8 + (threadIdx.x >> 5);
    int lane = threadIdx.x & 31;
    if (warp >= NPIX) return;
    const float* ap = g_a + (size_t)warp * F;

    float v[16];
#pragma unroll
    for (int j = 0; j < 16; j++) v[j] = ap[j * 32 + lane];

    unsigned u[16];
#pragma unroll
    for (int j = 0; j < 16; j++) u[j] = fkey(v[j]);

    // Batcher odd-even mergesort, 16 elements, descending (63 CEs)
    CE(0,1) CE(2,3) CE(4,5) CE(6,7) CE(8,9) CE(10,11) CE(12,13) CE(14,15)
    CE(0,2) CE(1,3) CE(4,6) CE(5,7) CE(8,10) CE(9,11) CE(12,14) CE(13,15)
    CE(1,2) CE(5,6) CE(9,10) CE(13,14)
    CE(0,4) CE(1,5) CE(2,6) CE(3,7) CE(8,12) CE(9,13) CE(10,14) CE(11,15)
    CE(2,4) CE(3,5) CE(10,12) CE(11,13)
    CE(1,2) CE(3,4) CE(5,6) CE(9,10) CE(11,12) CE(13,14)
    CE(0,8) CE(1,9) CE(2,10) CE(3,11) CE(4,12) CE(5,13) CE(6,14) CE(7,15)
    CE(4,8) CE(5,9) CE(6,10) CE(7,11)
    CE(2,4) CE(3,5) CE(6,8) CE(7,9) CE(10,12) CE(11,13)
    CE(1,2) CE(3,4) CE(5,6) CE(7,8) CE(9,10) CE(11,12) CE(13,14)

    int removed = 0;
    unsigned Tu = 0;
#pragma unroll 1
    for (int it = 0; it < 16; it++) {
        unsigned h = u[0];
        unsigned mx = __reduce_max_sync(0xffffffffu, h);
        int c = __popc(__ballot_sync(0xffffffffu, h == mx));
        Tu = mx;
        if (removed + c >= 16) break;
        removed += c;
        if (h == mx) {
#pragma unroll
            for (int j = 0; j < 15; j++) u[j] = u[j + 1];
            u[15] = 0u;
        }
    }

    int base = 0;
#pragma unroll
    for (int j = 0; j < 16; j++) {
        bool keep = fkey(v[j]) >= Tu;
        unsigned bal = __ballot_sync(0xffffffffu, keep);
        if (keep) {
            int pos = base + __popc(bal & ((1u << lane) - 1u));
            if (pos < 32) {
                g_spidx[warp * 32 + pos] = j * 32 + lane;
                g_spval[warp * 32 + pos] = v[j];
            }
        }
        base += __popc(bal);
    }
    if (lane == 0) g_spcnt[warp] = base < 32 ? base : 32;
}
#undef CE

// ------------------------- sparse adjoint recon + aux (float4/channel) -----
template<int CIN, int STRIDE, int HIN, bool L1>
__global__ void __launch_bounds__(256) recon_aux_kernel(const float* __restrict__ refp) {
    const int TPP = CIN / 4;            // threads per pixel
    const int PPB = 256 / TPP;          // pixels per block
    int tid = threadIdx.x;
    int cg = tid % TPP;
    int c0 = cg * 4;
    int pi = tid / TPP;
    int g = blockIdx.x * PPB + pi;
    int n = g / (HIN * HIN);
    int r = g - n * (HIN * HIN);
    int y = r / HIN, xx = r - y * HIN;
    const float* wrb = L1 ? g_wr1 : g_wr0;

    float4 recon = {0.f, 0.f, 0.f, 0.f};
#pragma unroll
    for (int ky = 0; ky < 3; ky++) {
        int t = y + 1 - ky;
        int oy;
        if (STRIDE == 2) { if (t & 1) continue; oy = t >> 1; } else oy = t;
        if ((unsigned)oy >= 28u) continue;
#pragma unroll
        for (int kx = 0; kx < 3; kx++) {
            int s = xx + 1 - kx;
            int ox;
            if (STRIDE == 2) { if (s & 1) continue; ox = s >> 1; } else ox = s;
            if ((unsigned)ox >= 28u) continue;
            int q = (n * 28 + oy) * 28 + ox;
            int cnt = g_spcnt[q];
            const float* wb = wrb + (size_t)(ky * 3 + kx) * F * CIN + c0;
            const int4*   ip = (const int4*)&g_spidx[q * 32];
            const float4* vp = (const float4*)&g_spval[q * 32];
            int nb = cnt >> 2;
            for (int b = 0; b < nb; b++) {
                int4   f4 = ip[b];
                float4 v4 = vp[b];
                float4 w0 = *(const float4*)&wb[f4.x * CIN];
                float4 w1 = *(const float4*)&wb[f4.y * CIN];
                float4 w2 = *(const float4*)&wb[f4.z * CIN];
                float4 w3 = *(const float4*)&wb[f4.w * CIN];
                recon.x += v4.x * w0.x; recon.y += v4.x * w0.y;
                recon.z += v4.x * w0.z; recon.w += v4.x * w0.w;
                recon.x += v4.y * w1.x; recon.y += v4.y * w1.y;
                recon.z += v4.y * w1.z; recon.w += v4.y * w1.w;
                recon.x += v4.z * w2.x; recon.y += v4.z * w2.y;
                recon.z += v4.z * w2.z; recon.w += v4.z * w2.w;
                recon.x += v4.w * w3.x; recon.y += v4.w * w3.y;
                recon.z += v4.w * w3.z; recon.w += v4.w * w3.w;
            }
            for (int e = nb * 4; e < cnt; e++) {
                float vv = g_spval[q * 32 + e];
                const float4 ww = *(const float4*)&wb[g_spidx[q * 32 + e] * CIN];
                recon.x += vv * ww.x; recon.y += vv * ww.y;
                recon.z += vv * ww.z; recon.w += vv * ww.w;
            }
        }
    }
    const float* refbase = L1 ? (const float*)g_out0 : refp;
    size_t ridx = ((size_t)(n * CIN + c0) * HIN + y) * HIN + xx;
    const size_t cs = (size_t)HIN * HIN;
    float d0 = recon.x - refbase[ridx];
    float d1 = recon.y - refbase[ridx + cs];
    float d2 = recon.z - refbase[ridx + 2 * cs];
    float d3 = recon.w - refbase[ridx + 3 * cs];
    float dd = d0 * d0 + d1 * d1 + d2 * d2 + d3 * d3;

    __shared__ float red[256];
    red[tid] = dd;
    __syncthreads();
    for (int st = 128; st > 0; st >>= 1) {
        if (tid < st) red[tid] += red[tid + st];
        __syncthreads();
    }
    if (tid == 0) g_partial[blockIdx.x] = red[0];
}

__global__ void reduce_partials(int n, float scale, float* __restrict__ out) {
    __shared__ float red[256];
    float s = 0.f;
    for (int i = threadIdx.x; i < n; i += 256) s += g_partial[i];
    red[threadIdx.x] = s;
    __syncthreads();
    for (int st = 128; st > 0; st >>= 1) {
        if (threadIdx.x < st) red[threadIdx.x] += red[threadIdx.x + st];
        __syncthreads();
    }
    if (threadIdx.x == 0) *out = red[0] * scale;
}

// ------------------------- sparse 1x1 projection (unrolled x4) -------------
__global__ void __launch_bounds__(256) proj_kernel(int slot) {
    float* out = (slot == 0) ? g_out0 : g_p1;
    const float* wp = (slot == 0) ? g_wpT0 : g_wpT1;
    int tid = threadIdx.x;
    int co = tid & 127;
    int pi = tid >> 7;
    int q = blockIdx.x * 2 + pi;
    int cnt = g_spcnt[q];
    const int4*   ip = (const int4*)&g_spidx[q * 32];
    const float4* vp = (const float4*)&g_spval[q * 32];
    float acc = 0.f;
    int nb = cnt >> 2;
    for (int b = 0; b < nb; b++) {
        int4   f4 = ip[b];
        float4 v4 = vp[b];
        float w0 = wp[f4.x * COUT + co];
        float w1 = wp[f4.y * COUT + co];
        float w2 = wp[f4.z * COUT + co];
        float w3 = wp[f4.w * COUT + co];
        acc += v4.x * w0;
        acc += v4.y * w1;
        acc += v4.z * w2;
        acc += v4.w * w3;
    }
    for (int e = nb * 4; e < cnt; e++)
        acc += g_spval[q * 32 + e] * wp[g_spidx[q * 32 + e] * COUT + co];
    int n = q / 784, r = q - n * 784;
    out[(size_t)(n * COUT + co) * 784 + r] = acc;
}

// ------------------------- shortcut 1x1 stride-2 ---------------------------
__global__ void __launch_bounds__(256) shortcut_kernel(const float* __restrict__ x) {
    int tid = threadIdx.x;
    int co = tid & 127;
    int pi = tid >> 7;
    int q = blockIdx.x * 2 + pi;
    int n = q / 784, r = q - n * 784;
    int oy = r / 28, ox = r - oy * 28;
    const float* xp = x + (size_t)n * 64 * 3136 + (2 * oy) * 56 + 2 * ox;
    float acc = 0.f;
#pragma unroll
    for (int c = 0; c < 64; c++) acc = fmaf(xp[c * 3136], g_wscT[c * 128 + co], acc);
    g_psc[(size_t)(n * COUT + co) * 784 + r] = acc;
}

// ------------------------- batchnorm stats (two-stage, double) -------------
__global__ void __launch_bounds__(256) bn_stage1(int slot) {
    const float* src = (slot == 0) ? g_out0 : (slot == 1 ? g_p1 : g_psc);
    int co = blockIdx.x;
    int chunk = blockIdx.y;
    int tid = threadIdx.x;
    double s = 0.0, s2 = 0.0;
    for (int n = chunk * 4; n < chunk * 4 + 4; n++) {
        const float* row = src + (size_t)(n * COUT + co) * 784;
        for (int r = tid; r < 784; r += 256) {
            double v = (double)row[r];
            s += v; s2 += v * v;
        }
    }
    __shared__ double rs[256], rq[256];
    rs[tid] = s; rq[tid] = s2;
    __syncthreads();
    for (int st = 128; st > 0; st >>= 1) {
        if (tid < st) { rs[tid] += rs[tid + st]; rq[tid] += rq[tid + st]; }
        __syncthreads();
    }
    if (tid == 0) g_bns[co * 16 + chunk] = make_double2(rs[0], rq[0]);
}
__global__ void bn_stage2(int slot) {
    int co = threadIdx.x;
    double s = 0.0, s2 = 0.0;
    for (int k = 0; k < 16; k++) {
        double2 p = g_bns[co * 16 + k];
        s += p.x; s2 += p.y;
    }
    double mean = s * (1.0 / 50176.0);
    double var = s2 * (1.0 / 50176.0) - mean * mean;
    g_mean[slot][co] = (float)mean;
    g_rstd[slot][co] = rsqrtf((float)var + BN_EPS);
}

__global__ void __launch_bounds__(256) norm0_kernel(const float* __restrict__ gg,
                                                    const float* __restrict__ bb) {
    size_t i = (size_t)blockIdx.x * 256 + threadIdx.x;
    if (i >= OUTN) return;
    int co = (int)((i / 784) & 127);
    g_out0[i] = ((g_out0[i] - g_mean[0][co]) * g_rstd[0][co]) * gg[co] + bb[co];
}

__global__ void __launch_bounds__(256) final_kernel(float* __restrict__ dout,
        const float* __restrict__ g1, const float* __restrict__ b1,
        const float* __restrict__ gsc, const float* __restrict__ bsc) {
    size_t i = (size_t)blockIdx.x * 256 + threadIdx.x;
    if (i >= OUTN) return;
    int co = (int)((i / 784) & 127);
    float v1 = ((g_p1[i]  - g_mean[1][co]) * g_rstd[1][co]) * g1[co]  + b1[co];
    float v2 = ((g_psc[i] - g_mean[2][co]) * g_rstd[2][co]) * gsc[co] + bsc[co];
    float v = v1 + v2;
    dout[i] = v > 0.f ? v : 0.f;
}

// ---------------------------------------------------------------------------
extern "C" void kernel_launch(void* const* d_in, const int* in_sizes, int n_in,
                              void* d_out, int out_size) {
    const float* x       = (const float*)d_in[0];
    const float* w_enc0  = (const float*)d_in[1];
    const float* w_proj0 = (const float*)d_in[2];
    const float* g0      = (const float*)d_in[3];
    const float* b0      = (const float*)d_in[4];
    const float* w_enc1  = (const float*)d_in[5];
    const float* w_proj1 = (const float*)d_in[6];
    const float* g1      = (const float*)d_in[7];
    const float* b1      = (const float*)d_in[8];
    const float* w_sc    = (const float*)d_in[9];
    const float* g_sc    = (const float*)d_in[10];
    const float* b_sc    = (const float*)d_in[11];
    float* out = (float*)d_out;

    const int elem_blocks = (int)((OUTN + 255) / 256);
    dim3 bnGrid(128, 16);

    // ---------------- layer 0 ----------------
    prep_enc<<<(9 * 512 * 64 + 255) / 256, 256>>>(w_enc0, 64, 0);     // #1
    make_wpT<<<(512 * 128 + 255) / 256, 256>>>(w_proj0, 0);           // #2
    make_wscT<<<(64 * 128 + 255) / 256, 256>>>(w_sc);                 // #3
    conv_enc<64, 2, 56, false><<<dim3(NPIX / 128, 4), 128>>>(x);      // #4 <- profiled
    topk_kernel<<<NPIX / 8, 256>>>();
    recon_aux_kernel<64, 2, 56, false><<<NIMG * 3136 / 16, 256>>>(x);
    reduce_partials<<<1, 256>>>(NIMG * 3136 / 16, 1.f / 12845056.f, out + out_size - 2);
    proj_kernel<<<NPIX / 2, 256>>>(0);
    bn_stage1<<<bnGrid, 256>>>(0);
    bn_stage2<<<1, 128>>>(0);
    norm0_kernel<<<elem_blocks, 256>>>(g0, b0);

    // ---------------- layer 1 ----------------
    prep_enc<<<(9 * 512 * 128 + 255) / 256, 256>>>(w_enc1, 128, 1);
    conv_enc<128, 1, 28, true><<<dim3(NPIX / 128, 4), 128>>>(x);
    topk_kernel<<<NPIX / 8, 256>>>();
    recon_aux_kernel<128, 1, 28, true><<<NIMG * 784 / 8, 256>>>(nullptr);
    reduce_partials<<<1, 256>>>(NIMG * 784 / 8, 1.f / 6422528.f, out + out_size - 1);
    make_wpT<<<(512 * 128 + 255) / 256, 256>>>(w_proj1, 1);
    proj_kernel<<<NPIX / 2, 256>>>(1);
    bn_stage1<<<bnGrid, 256>>>(1);
    bn_stage2<<<1, 128>>>(1);

    // ---------------- shortcut + fuse ----------------
    shortcut_kernel<<<NPIX / 2, 256>>>(x);
    bn_stage1<<<bnGrid, 256>>>(2);
    bn_stage2<<<1, 128>>>(2);
    final_kernel<<<elem_blocks, 256>>>(out, g1, b1, g_sc, b_sc);
}